// round 12
// baseline (speedup 1.0000x reference)
#include <cuda_runtime.h>
#include <cuda_fp16.h>
#include <cstdint>

#define GROUPS  2048
#define NT      16
#define SW      36    // smem row stride in 32-bit words (= 72 halves = 144 B)

__device__ __forceinline__ uint32_t pack2h(float lo, float hi) {
    __half2 h = __floats2half2_rn(lo, hi);
    return *reinterpret_cast<uint32_t*>(&h);
}

__device__ __forceinline__ void mma_f16(float& d0, float& d1, float& d2, float& d3,
                                        uint32_t a0, uint32_t a1, uint32_t a2, uint32_t a3,
                                        uint32_t b0, uint32_t b1) {
    asm volatile("mma.sync.aligned.m16n8k16.row.col.f32.f16.f16.f32 "
                 "{%0,%1,%2,%3}, {%4,%5,%6,%7}, {%8,%9}, {%0,%1,%2,%3};"
                 : "+f"(d0), "+f"(d1), "+f"(d2), "+f"(d3)
                 : "r"(a0), "r"(a1), "r"(a2), "r"(a3), "r"(b0), "r"(b1));
}

// fp16, 2 CTAs/SM, one CTA per group, 256 threads, warp tile m16 x n32.
// Warps w and w+4 share rows, split cols. Layer-1 A-fragments for the warp's
// OWN 2 k-chunks come straight from its layer-0 accumulators (C-frag layout ==
// A-frag layout); only the partner's 2 k-chunks are read from smem -> h smem
// reads halved, first half of layer-1 issues with zero loads. Biases read from
// smem (broadcast) to keep regs <= 128 for 2-CTA residency.
extern "C" __global__ void __launch_bounds__(256, 2) convnn_r12(
    const float* __restrict__ x,  const float* __restrict__ W0,
    const float* __restrict__ b0, const float* __restrict__ W1,
    const float* __restrict__ b1, float* __restrict__ out)
{
    __shared__ uint32_t sX[64 * SW];
    __shared__ uint32_t sH[64 * SW];
    __shared__ float    sB0[64], sB1[64];

    const int g    = blockIdx.x;
    const int tid  = threadIdx.x;
    const int lane = tid & 31;
    const int warp = tid >> 5;
    const int gid  = lane >> 2;
    const int tig  = lane & 3;
    const int mrow  = (warp & 3) * 16;
    const int jbase = (warp >> 2) * 32;   // 0 or 32
    const int r0    = mrow + gid;
    const int kcown = (jbase >> 5) * 2;   // own k-chunks: kcown, kcown+1

    const int sr = tid >> 4;          // staging row 0..15 (+16*rr)
    const int c4 = (tid & 15) << 2;   // staging col base (floats)

    // ---- stage W0/W1 (fp16) through sX, pull this warp's B-frags ----
    uint32_t wf[2][4][4][2];
    #pragma unroll
    for (int layer = 0; layer < 2; layer++) {
        const float* W = (layer ? W1 : W0) + (size_t)g * 64 * 64;
        #pragma unroll
        for (int rr = 0; rr < 4; rr++) {
            const int row = sr + rr * 16;
            float4 w = *(const float4*)(W + (size_t)row * 64 + c4);
            *(uint2*)&sX[row * SW + (c4 >> 1)] =
                make_uint2(pack2h(w.x, w.y), pack2h(w.z, w.w));
        }
        __syncthreads();
        #pragma unroll
        for (int s = 0; s < 4; s++) {
            const int jr = (jbase + s * 8 + gid) * SW;
            #pragma unroll
            for (int kc = 0; kc < 4; kc++) {
                wf[layer][s][kc][0] = sX[jr + kc * 8 + tig];
                wf[layer][s][kc][1] = sX[jr + kc * 8 + 4 + tig];
            }
        }
        __syncthreads();
    }
    if (tid < 64)       sB0[tid]      = b0[(size_t)g * 64 + tid];
    else if (tid < 128) sB1[tid - 64] = b1[(size_t)g * 64 + (tid - 64)];
    // sB* consumed only after the bar1 inside the loop

    // ---- prefetch first X tile, pre-packed to half2 ----
    uint2 px[4];
    #pragma unroll
    for (int rr = 0; rr < 4; rr++) {
        float4 v = *(const float4*)(x + (size_t)(sr + rr * 16) * 64 + c4);
        px[rr] = make_uint2(pack2h(v.x, v.y), pack2h(v.z, v.w));
    }

    for (int it = 0; it < NT; it++) {
        // store X tile (fp16) -- L0(t-1) X reads finished before bar2(t-1)
        #pragma unroll
        for (int rr = 0; rr < 4; rr++)
            *(uint2*)&sX[(sr + rr * 16) * SW + (c4 >> 1)] = px[rr];
        __syncthreads();   // bar1: X visible; L1(t-1) h-reads < epi0(t) h-writes

        // prefetch next tile (pre-packed)
        if (it + 1 < NT) {
            const float* xs = x + (size_t)(it + 1) * 4096;
            #pragma unroll
            for (int rr = 0; rr < 4; rr++) {
                float4 v = *(const float4*)(xs + (size_t)(sr + rr * 16) * 64 + c4);
                px[rr] = make_uint2(pack2h(v.x, v.y), pack2h(v.z, v.w));
            }
        }

        float acc[4][4];
        #pragma unroll
        for (int s = 0; s < 4; s++)
            #pragma unroll
            for (int i = 0; i < 4; i++) acc[s][i] = 0.f;

        // ===== layer 0: acc = X * W0^T =====
        #pragma unroll
        for (int kc = 0; kc < 4; kc++) {
            const int kw = kc * 8 + tig;
            const uint32_t a0 = sX[(r0)     * SW + kw];
            const uint32_t a1 = sX[(r0 + 8) * SW + kw];
            const uint32_t a2 = sX[(r0)     * SW + kw + 4];
            const uint32_t a3 = sX[(r0 + 8) * SW + kw + 4];
            #pragma unroll
            for (int s = 0; s < 4; s++)
                mma_f16(acc[s][0], acc[s][1], acc[s][2], acc[s][3],
                        a0, a1, a2, a3, wf[0][s][kc][0], wf[0][s][kc][1]);
        }

        // ===== epilogue 0: bias + LeakyReLU; write h to sH (for partner warp)
        //       and keep own-col A-fragments in registers =====
        uint32_t ha[2][4];   // [local k-chunk][a0..a3]
        #pragma unroll
        for (int s = 0; s < 4; s++) {
            const int jw = (jbase >> 1) + s * 4 + tig;
            const float2 bb = *(const float2*)&sB0[jbase + s * 8 + 2 * tig];
            float h00 = acc[s][0] + bb.x; h00 = (h00 > 0.f) ? h00 : 0.2f * h00;
            float h01 = acc[s][1] + bb.y; h01 = (h01 > 0.f) ? h01 : 0.2f * h01;
            float h10 = acc[s][2] + bb.x; h10 = (h10 > 0.f) ? h10 : 0.2f * h10;
            float h11 = acc[s][3] + bb.y; h11 = (h11 > 0.f) ? h11 : 0.2f * h11;
            const uint32_t p0 = pack2h(h00, h01);
            const uint32_t p1 = pack2h(h10, h11);
            sH[(r0)     * SW + jw] = p0;
            sH[(r0 + 8) * SW + jw] = p1;
            // own cols [jbase+s*8, +8) = k-half (s&1) of local chunk s>>1
            ha[s >> 1][(s & 1) * 2 + 0] = p0;
            ha[s >> 1][(s & 1) * 2 + 1] = p1;
        }
        __syncthreads();   // bar2: h visible; all L0 X-reads < storeX(t+1)

        // ===== layer 1: acc = h * W1^T =====
        #pragma unroll
        for (int s = 0; s < 4; s++)
            #pragma unroll
            for (int i = 0; i < 4; i++) acc[s][i] = 0.f;

        // own chunks first: zero loads, issues immediately after the barrier
        #pragma unroll
        for (int kl = 0; kl < 2; kl++) {
            const int kc = kcown + kl;
            #pragma unroll
            for (int s = 0; s < 4; s++)
                mma_f16(acc[s][0], acc[s][1], acc[s][2], acc[s][3],
                        ha[kl][0], ha[kl][1], ha[kl][2], ha[kl][3],
                        wf[1][s][kc][0], wf[1][s][kc][1]);
        }
        // partner chunks from smem
        #pragma unroll
        for (int kl = 0; kl < 2; kl++) {
            const int kc = (kcown ^ 2) + kl;
            const int kw = kc * 8 + tig;
            const uint32_t a0 = sH[(r0)     * SW + kw];
            const uint32_t a1 = sH[(r0 + 8) * SW + kw];
            const uint32_t a2 = sH[(r0)     * SW + kw + 4];
            const uint32_t a3 = sH[(r0 + 8) * SW + kw + 4];
            #pragma unroll
            for (int s = 0; s < 4; s++)
                mma_f16(acc[s][0], acc[s][1], acc[s][2], acc[s][3],
                        a0, a1, a2, a3, wf[1][s][kc][0], wf[1][s][kc][1]);
        }

        // epilogue 1: bias (smem broadcast), 32B-sector float2 stores
        const int brow = it * 64 + r0;
        #pragma unroll
        for (int s = 0; s < 4; s++) {
            const int j = jbase + s * 8 + 2 * tig;
            const float2 bb = *(const float2*)&sB1[j];
            float2 v0 = make_float2(acc[s][0] + bb.x, acc[s][1] + bb.y);
            float2 v1 = make_float2(acc[s][2] + bb.x, acc[s][3] + bb.y);
            *(float2*)(out + ((size_t)brow       * GROUPS + g) * 64 + j) = v0;
            *(float2*)(out + ((size_t)(brow + 8) * GROUPS + g) * 64 + j) = v1;
        }
    }
}

extern "C" void kernel_launch(void* const* d_in, const int* in_sizes, int n_in,
                              void* d_out, int out_size) {
    const float* x  = (const float*)d_in[0];
    const float* W0 = (const float*)d_in[1];
    const float* b0 = (const float*)d_in[2];
    const float* W1 = (const float*)d_in[3];
    const float* b1 = (const float*)d_in[4];
    float* out = (float*)d_out;

    convnn_r12<<<GROUPS, 256>>>(x, W0, b0, W1, b1, out);
}

// round 13
// speedup vs baseline: 1.1242x; 1.1242x over previous
#include <cuda_runtime.h>
#include <cuda_fp16.h>
#include <cstdint>

#define GROUPS  2048
#define NT      16
#define SW      36    // smem row stride in 32-bit words (= 72 halves = 144 B)

__device__ __forceinline__ uint32_t pack2h(float lo, float hi) {
    __half2 h = __floats2half2_rn(lo, hi);
    return *reinterpret_cast<uint32_t*>(&h);
}

__device__ __forceinline__ void mma_f16(float& d0, float& d1, float& d2, float& d3,
                                        uint32_t a0, uint32_t a1, uint32_t a2, uint32_t a3,
                                        uint32_t b0, uint32_t b1) {
    asm volatile("mma.sync.aligned.m16n8k16.row.col.f32.f16.f16.f32 "
                 "{%0,%1,%2,%3}, {%4,%5,%6,%7}, {%8,%9}, {%0,%1,%2,%3};"
                 : "+f"(d0), "+f"(d1), "+f"(d2), "+f"(d3)
                 : "r"(a0), "r"(a1), "r"(a2), "r"(a3), "r"(b0), "r"(b1));
}

__device__ __forceinline__ void barp(int id) {
    asm volatile("bar.sync %0, %1;" :: "r"(id), "r"(64) : "memory");
}

// fp16, 2 CTAs/SM, one CTA per group, 256 threads, warp tile m16 x n32.
// The CTA is split into 4 INDEPENDENT 2-warp pipelines: pair p = warps {p, p+4}
// exclusively owns X rows [16p,16p+16) and h rows [16p,16p+16). Pair stages its
// own X rows; both per-iter barriers are pair-scoped named barriers (bar.sync
// p+1, 64). No full-CTA barrier in the main loop -> slow-warp variance no
// longer serializes the whole CTA. Weight/bias prologue keeps __syncthreads.
extern "C" __global__ void __launch_bounds__(256, 2) convnn_r13(
    const float* __restrict__ x,  const float* __restrict__ W0,
    const float* __restrict__ b0, const float* __restrict__ W1,
    const float* __restrict__ b1, float* __restrict__ out)
{
    __shared__ uint32_t sX[64 * SW];
    __shared__ uint32_t sH[64 * SW];
    __shared__ float    sB0[64], sB1[64];

    const int g    = blockIdx.x;
    const int tid  = threadIdx.x;
    const int lane = tid & 31;
    const int warp = tid >> 5;
    const int gid  = lane >> 2;
    const int tig  = lane & 3;
    const int p     = warp & 3;          // pair id 0..3
    const int half  = warp >> 2;         // 0 or 1 within pair
    const int mrow  = p * 16;
    const int jbase = half * 32;
    const int r0    = mrow + gid;
    const int l     = half * 32 + lane;  // pair-local thread index 0..63

    // pair-local staging map: 16 rows x 64 floats, 64 threads x 4 float4
    const int rstage = mrow + (l >> 2);        // own pair's rows only
    const int cq     = (l & 3) * 4;            // float col within 16-col stripe

    // ---- prologue (full-CTA): stage W0/W1 (fp16) through sX, pull B-frags ----
    uint32_t wf[2][4][4][2];
    {
        const int sr = tid >> 4;
        const int c4 = (tid & 15) << 2;
        #pragma unroll
        for (int layer = 0; layer < 2; layer++) {
            const float* W = (layer ? W1 : W0) + (size_t)g * 64 * 64;
            #pragma unroll
            for (int rr = 0; rr < 4; rr++) {
                const int row = sr + rr * 16;
                float4 w = *(const float4*)(W + (size_t)row * 64 + c4);
                *(uint2*)&sX[row * SW + (c4 >> 1)] =
                    make_uint2(pack2h(w.x, w.y), pack2h(w.z, w.w));
            }
            __syncthreads();
            #pragma unroll
            for (int s = 0; s < 4; s++) {
                const int jr = (jbase + s * 8 + gid) * SW;
                #pragma unroll
                for (int kc = 0; kc < 4; kc++) {
                    wf[layer][s][kc][0] = sX[jr + kc * 8 + tig];
                    wf[layer][s][kc][1] = sX[jr + kc * 8 + 4 + tig];
                }
            }
            __syncthreads();
        }
        if (tid < 64)       sB0[tid]      = b0[(size_t)g * 64 + tid];
        else if (tid < 128) sB1[tid - 64] = b1[(size_t)g * 64 + (tid - 64)];
        __syncthreads();   // biases visible; pairs run free from here on
    }

    // ---- prefetch first X tile (pair rows), packed ----
    uint2 px[4];
    #pragma unroll
    for (int q = 0; q < 4; q++) {
        float4 v = *(const float4*)(x + (size_t)rstage * 64 + q * 16 + cq);
        px[q] = make_uint2(pack2h(v.x, v.y), pack2h(v.z, v.w));
    }

    for (int it = 0; it < NT; it++) {
        // store own pair's X rows (fp16)
        #pragma unroll
        for (int q = 0; q < 4; q++)
            sX[rstage * SW + q * 8 + ((cq >> 1) & 7)] = px[q].x,
            sX[rstage * SW + q * 8 + ((cq >> 1) & 7) + 1] = px[q].y;
        barp(p + 1);   // pairbar1: X rows visible; L1(t-1) h-reads < epi0(t) writes

        // prefetch next tile (pair rows)
        if (it + 1 < NT) {
            const float* xs = x + (size_t)(it + 1) * 4096;
            #pragma unroll
            for (int q = 0; q < 4; q++) {
                float4 v = *(const float4*)(xs + (size_t)rstage * 64 + q * 16 + cq);
                px[q] = make_uint2(pack2h(v.x, v.y), pack2h(v.z, v.w));
            }
        }

        float acc[4][4];
        #pragma unroll
        for (int s = 0; s < 4; s++)
            #pragma unroll
            for (int i = 0; i < 4; i++) acc[s][i] = 0.f;

        // ===== layer 0: acc = X * W0^T =====
        #pragma unroll
        for (int kc = 0; kc < 4; kc++) {
            const int kw = kc * 8 + tig;
            const uint32_t a0 = sX[(r0)     * SW + kw];
            const uint32_t a1 = sX[(r0 + 8) * SW + kw];
            const uint32_t a2 = sX[(r0)     * SW + kw + 4];
            const uint32_t a3 = sX[(r0 + 8) * SW + kw + 4];
            #pragma unroll
            for (int s = 0; s < 4; s++)
                mma_f16(acc[s][0], acc[s][1], acc[s][2], acc[s][3],
                        a0, a1, a2, a3, wf[0][s][kc][0], wf[0][s][kc][1]);
        }

        // epilogue 0: bias + LeakyReLU -> h (fp16) rows r0/r0+8, cols jbase..+32
        #pragma unroll
        for (int s = 0; s < 4; s++) {
            const int jw = (jbase >> 1) + s * 4 + tig;
            const float2 bb = *(const float2*)&sB0[jbase + s * 8 + 2 * tig];
            float h00 = acc[s][0] + bb.x; h00 = (h00 > 0.f) ? h00 : 0.2f * h00;
            float h01 = acc[s][1] + bb.y; h01 = (h01 > 0.f) ? h01 : 0.2f * h01;
            float h10 = acc[s][2] + bb.x; h10 = (h10 > 0.f) ? h10 : 0.2f * h10;
            float h11 = acc[s][3] + bb.y; h11 = (h11 > 0.f) ? h11 : 0.2f * h11;
            sH[(r0)     * SW + jw] = pack2h(h00, h01);
            sH[(r0 + 8) * SW + jw] = pack2h(h10, h11);
        }
        barp(p + 1);   // pairbar2: h visible; pair's L0 X-reads < storeX(t+1)

        // ===== layer 1: acc = h * W1^T =====
        #pragma unroll
        for (int s = 0; s < 4; s++)
            #pragma unroll
            for (int i = 0; i < 4; i++) acc[s][i] = 0.f;

        #pragma unroll
        for (int kc = 0; kc < 4; kc++) {
            const int kw = kc * 8 + tig;
            const uint32_t a0 = sH[(r0)     * SW + kw];
            const uint32_t a1 = sH[(r0 + 8) * SW + kw];
            const uint32_t a2 = sH[(r0)     * SW + kw + 4];
            const uint32_t a3 = sH[(r0 + 8) * SW + kw + 4];
            #pragma unroll
            for (int s = 0; s < 4; s++)
                mma_f16(acc[s][0], acc[s][1], acc[s][2], acc[s][3],
                        a0, a1, a2, a3, wf[1][s][kc][0], wf[1][s][kc][1]);
        }

        // epilogue 1: bias, 32B-sector float2 stores
        const int brow = it * 64 + r0;
        #pragma unroll
        for (int s = 0; s < 4; s++) {
            const int j = jbase + s * 8 + 2 * tig;
            const float2 bb = *(const float2*)&sB1[j];
            float2 v0 = make_float2(acc[s][0] + bb.x, acc[s][1] + bb.y);
            float2 v1 = make_float2(acc[s][2] + bb.x, acc[s][3] + bb.y);
            *(float2*)(out + ((size_t)brow       * GROUPS + g) * 64 + j) = v0;
            *(float2*)(out + ((size_t)(brow + 8) * GROUPS + g) * 64 + j) = v1;
        }
    }
}

extern "C" void kernel_launch(void* const* d_in, const int* in_sizes, int n_in,
                              void* d_out, int out_size) {
    const float* x  = (const float*)d_in[0];
    const float* W0 = (const float*)d_in[1];
    const float* b0 = (const float*)d_in[2];
    const float* W1 = (const float*)d_in[3];
    const float* b1 = (const float*)d_in[4];
    float* out = (float*)d_out;

    convnn_r13<<<GROUPS, 256>>>(x, W0, b0, W1, b1, out);
}

// round 15
// speedup vs baseline: 1.2854x; 1.1433x over previous
#include <cuda_runtime.h>
#include <cuda_fp16.h>
#include <cstdint>

#define GROUPS  2048
#define NT      16
#define SW      36    // smem row stride in 32-bit words (= 72 halves = 144 B)

__device__ __align__(16) __half xh_g[1024 * 64];   // x pre-converted to fp16

__device__ __forceinline__ uint32_t pack2h(float lo, float hi) {
    __half2 h = __floats2half2_rn(lo, hi);
    return *reinterpret_cast<uint32_t*>(&h);
}

__device__ __forceinline__ uint32_t smem_u32(const void* p) {
    uint32_t a;
    asm("{ .reg .u64 t; cvta.to.shared.u64 t, %1; cvt.u32.u64 %0, t; }" : "=r"(a) : "l"(p));
    return a;
}

__device__ __forceinline__ void cpasync16(uint32_t saddr, const void* g) {
    asm volatile("cp.async.cg.shared.global [%0], [%1], 16;" :: "r"(saddr), "l"(g) : "memory");
}
#define CP_COMMIT() asm volatile("cp.async.commit_group;" ::: "memory")
#define CP_WAIT0()  asm volatile("cp.async.wait_group 0;" ::: "memory")

__device__ __forceinline__ void mma_f16(float& d0, float& d1, float& d2, float& d3,
                                        uint32_t a0, uint32_t a1, uint32_t a2, uint32_t a3,
                                        uint32_t b0, uint32_t b1) {
    asm volatile("mma.sync.aligned.m16n8k16.row.col.f32.f16.f16.f32 "
                 "{%0,%1,%2,%3}, {%4,%5,%6,%7}, {%8,%9}, {%0,%1,%2,%3};"
                 : "+f"(d0), "+f"(d1), "+f"(d2), "+f"(d3)
                 : "r"(a0), "r"(a1), "r"(a2), "r"(a3), "r"(b0), "r"(b1));
}

// pre-pass: x (f32) -> xh_g (fp16), 16384 float4s
extern "C" __global__ void cvt_x_kernel(const float* __restrict__ x) {
    const int i = blockIdx.x * blockDim.x + threadIdx.x;   // 0..16383
    float4 v = ((const float4*)x)[i];
    ((uint2*)xh_g)[i] = make_uint2(pack2h(v.x, v.y), pack2h(v.z, v.w));
}

// R10 structure: fp16, 2 CTAs/SM, one CTA per group, 256 threads, warp tile
// m16 x n32, weight frags in regs, separate sX/sH, two barriers per iter.
// Delta vs R10: X staged by cp.async.cg from pre-converted fp16 x (no LDG/cvt/
// STS chain, no prefetch registers); epilogue-0 in half2 (hmax leaky).
extern "C" __global__ void __launch_bounds__(256, 2) convnn_r14(
    const float* __restrict__ x,  const float* __restrict__ W0,
    const float* __restrict__ b0, const float* __restrict__ W1,
    const float* __restrict__ b1, float* __restrict__ out)
{
    __shared__ uint32_t sX[64 * SW];
    __shared__ uint32_t sH[64 * SW];
    __shared__ uint32_t sB0h[32];      // b0 as half2 pairs
    __shared__ float    sB1[64];

    const int g    = blockIdx.x;
    const int tid  = threadIdx.x;
    const int lane = tid & 31;
    const int warp = tid >> 5;
    const int gid  = lane >> 2;
    const int tig  = lane & 3;
    const int mrow  = (warp & 3) * 16;
    const int jbase = (warp >> 2) * 32;
    const int r0    = mrow + gid;

    const uint32_t sXa = smem_u32(sX);
    // cp.async chunk map: chunk c -> row c>>3, 16B block c&7
    const int crow0 = tid >> 3,        ccol0 = (tid & 7) * 16;
    const int crow1 = (tid + 256) >> 3, ccol1 = ccol0;   // chunk tid+256: same col, row+32

    // ---- stage W0/W1 (fp16) through sX, pull this warp's B-frags ----
    uint32_t wf[2][4][4][2];
    {
        const int sr = tid >> 4;
        const int c4 = (tid & 15) << 2;
        #pragma unroll
        for (int layer = 0; layer < 2; layer++) {
            const float* W = (layer ? W1 : W0) + (size_t)g * 64 * 64;
            #pragma unroll
            for (int rr = 0; rr < 4; rr++) {
                const int row = sr + rr * 16;
                float4 w = *(const float4*)(W + (size_t)row * 64 + c4);
                *(uint2*)&sX[row * SW + (c4 >> 1)] =
                    make_uint2(pack2h(w.x, w.y), pack2h(w.z, w.w));
            }
            __syncthreads();
            #pragma unroll
            for (int s = 0; s < 4; s++) {
                const int jr = (jbase + s * 8 + gid) * SW;
                #pragma unroll
                for (int kc = 0; kc < 4; kc++) {
                    wf[layer][s][kc][0] = sX[jr + kc * 8 + tig];
                    wf[layer][s][kc][1] = sX[jr + kc * 8 + 4 + tig];
                }
            }
            __syncthreads();
        }
    }
    if (tid < 32)        sB0h[tid]     = pack2h(b0[(size_t)g * 64 + 2 * tid],
                                                b0[(size_t)g * 64 + 2 * tid + 1]);
    else if (tid < 96)   sB1[tid - 32] = b1[(size_t)g * 64 + (tid - 32)];
    // consumed only after bar1 below

    // ---- preloop: issue cp.async for tile 0 ----
    {
        const char* src = (const char*)xh_g;
        cpasync16(sXa + (uint32_t)(crow0 * 144 + ccol0), src + crow0 * 128 + ccol0);
        cpasync16(sXa + (uint32_t)(crow1 * 144 + ccol1), src + crow1 * 128 + ccol1);
        CP_COMMIT();
    }

    const __half2 k02 = __half2half2(__float2half(0.2f));

    for (int it = 0; it < NT; it++) {
        CP_WAIT0();
        __syncthreads();   // bar1: X(t) visible; L1(t-1) h-reads < epi0(t) h-writes

        float acc[4][4];
        #pragma unroll
        for (int s = 0; s < 4; s++)
            #pragma unroll
            for (int i = 0; i < 4; i++) acc[s][i] = 0.f;

        // ===== layer 0: acc = X * W0^T =====
        #pragma unroll
        for (int kc = 0; kc < 4; kc++) {
            const int kw = kc * 8 + tig;
            const uint32_t a0 = sX[(r0)     * SW + kw];
            const uint32_t a1 = sX[(r0 + 8) * SW + kw];
            const uint32_t a2 = sX[(r0)     * SW + kw + 4];
            const uint32_t a3 = sX[(r0 + 8) * SW + kw + 4];
            #pragma unroll
            for (int s = 0; s < 4; s++)
                mma_f16(acc[s][0], acc[s][1], acc[s][2], acc[s][3],
                        a0, a1, a2, a3, wf[0][s][kc][0], wf[0][s][kc][1]);
        }

        // epilogue 0 (half2): h = max(v, 0.2*v), v = f16(acc) + b0
        #pragma unroll
        for (int s = 0; s < 4; s++) {
            const int jw = (jbase >> 1) + s * 4 + tig;
            const __half2 hb = *(const __half2*)&sB0h[jw];
            __half2 p0 = __hadd2(__floats2half2_rn(acc[s][0], acc[s][1]), hb);
            __half2 p1 = __hadd2(__floats2half2_rn(acc[s][2], acc[s][3]), hb);
            p0 = __hmax2(p0, __hmul2(p0, k02));
            p1 = __hmax2(p1, __hmul2(p1, k02));
            sH[(r0)     * SW + jw] = *(uint32_t*)&p0;
            sH[(r0 + 8) * SW + jw] = *(uint32_t*)&p1;
        }
        __syncthreads();   // bar2: h visible; all L0 X-reads < cp.async X(t+1)

        // issue cp.async for X(t+1); overlaps layer 1 + epilogue 1
        if (it + 1 < NT) {
            const char* src = (const char*)xh_g + (size_t)(it + 1) * 8192;
            cpasync16(sXa + (uint32_t)(crow0 * 144 + ccol0), src + crow0 * 128 + ccol0);
            cpasync16(sXa + (uint32_t)(crow1 * 144 + ccol1), src + crow1 * 128 + ccol1);
            CP_COMMIT();
        }

        // ===== layer 1: acc = h * W1^T =====
        #pragma unroll
        for (int s = 0; s < 4; s++)
            #pragma unroll
            for (int i = 0; i < 4; i++) acc[s][i] = 0.f;

        #pragma unroll
        for (int kc = 0; kc < 4; kc++) {
            const int kw = kc * 8 + tig;
            const uint32_t a0 = sH[(r0)     * SW + kw];
            const uint32_t a1 = sH[(r0 + 8) * SW + kw];
            const uint32_t a2 = sH[(r0)     * SW + kw + 4];
            const uint32_t a3 = sH[(r0 + 8) * SW + kw + 4];
            #pragma unroll
            for (int s = 0; s < 4; s++)
                mma_f16(acc[s][0], acc[s][1], acc[s][2], acc[s][3],
                        a0, a1, a2, a3, wf[1][s][kc][0], wf[1][s][kc][1]);
        }

        // epilogue 1: fp32 bias, 32B-sector float2 stores
        const int brow = it * 64 + r0;
        #pragma unroll
        for (int s = 0; s < 4; s++) {
            const int j = jbase + s * 8 + 2 * tig;
            const float2 bb = *(const float2*)&sB1[j];
            float2 v0 = make_float2(acc[s][0] + bb.x, acc[s][1] + bb.y);
            float2 v1 = make_float2(acc[s][2] + bb.x, acc[s][3] + bb.y);
            *(float2*)(out + ((size_t)brow       * GROUPS + g) * 64 + j) = v0;
            *(float2*)(out + ((size_t)(brow + 8) * GROUPS + g) * 64 + j) = v1;
        }
    }
}

extern "C" void kernel_launch(void* const* d_in, const int* in_sizes, int n_in,
                              void* d_out, int out_size) {
    const float* x  = (const float*)d_in[0];
    const float* W0 = (const float*)d_in[1];
    const float* b0 = (const float*)d_in[2];
    const float* W1 = (const float*)d_in[3];
    const float* b1 = (const float*)d_in[4];
    float* out = (float*)d_out;

    cvt_x_kernel<<<64, 256>>>(x);
    convnn_r14<<<GROUPS, 256>>>(x, W0, b0, W1, b1, out);
}

// round 16
// speedup vs baseline: 1.3258x; 1.0314x over previous
#include <cuda_runtime.h>
#include <cuda_fp16.h>
#include <cstdint>

#define GROUPS  2048
#define NT      16
#define SW      36    // smem row stride in 32-bit words (144 B)
#define BUFW    (64 * SW)

__device__ __align__(16) __half xh_g[1024 * 64];   // x pre-converted to fp16

__device__ __forceinline__ uint32_t pack2h(float lo, float hi) {
    __half2 h = __floats2half2_rn(lo, hi);
    return *reinterpret_cast<uint32_t*>(&h);
}
__device__ __forceinline__ uint32_t smem_u32(const void* p) {
    uint32_t a;
    asm("{ .reg .u64 t; cvta.to.shared.u64 t, %1; cvt.u32.u64 %0, t; }" : "=r"(a) : "l"(p));
    return a;
}
__device__ __forceinline__ void cpasync16(uint32_t saddr, const void* g) {
    asm volatile("cp.async.cg.shared.global [%0], [%1], 16;" :: "r"(saddr), "l"(g) : "memory");
}
#define CP_COMMIT() asm volatile("cp.async.commit_group;" ::: "memory")
#define CP_WAIT0()  asm volatile("cp.async.wait_group 0;" ::: "memory")

__device__ __forceinline__ void mma_f16(float& d0, float& d1, float& d2, float& d3,
                                        uint32_t a0, uint32_t a1, uint32_t a2, uint32_t a3,
                                        uint32_t b0, uint32_t b1) {
    asm volatile("mma.sync.aligned.m16n8k16.row.col.f32.f16.f16.f32 "
                 "{%0,%1,%2,%3}, {%4,%5,%6,%7}, {%8,%9}, {%0,%1,%2,%3};"
                 : "+f"(d0), "+f"(d1), "+f"(d2), "+f"(d3)
                 : "r"(a0), "r"(a1), "r"(a2), "r"(a3), "r"(b0), "r"(b1));
}

extern "C" __global__ void cvt_x_kernel(const float* __restrict__ x) {
    const int i = blockIdx.x * blockDim.x + threadIdx.x;   // 0..16383
    float4 v = ((const float4*)x)[i];
    ((uint2*)xh_g)[i] = make_uint2(pack2h(v.x, v.y), pack2h(v.z, v.w));
}

// fp16, 2 CTAs/SM, 256 threads, warp tile m16 x n32, weight frags in regs.
// Cross-iteration pipeline: within one barrier interval each warp runs
// L1(t-1) AND L0(t) (two independent MMA/LDS streams, 8 acc chains), with
// sX and sH double-buffered and ONE __syncthreads per iteration (placed
// after the cp.async wait: makes X(t) and h(t-1) visible simultaneously).
extern "C" __global__ void __launch_bounds__(256, 2) convnn_r16(
    const float* __restrict__ x,  const float* __restrict__ W0,
    const float* __restrict__ b0, const float* __restrict__ W1,
    const float* __restrict__ b1, float* __restrict__ out)
{
    __shared__ uint32_t sX[2][BUFW];
    __shared__ uint32_t sH[2][BUFW];
    __shared__ uint32_t sB0h[32];
    __shared__ float    sB1[64];

    const int g    = blockIdx.x;
    const int tid  = threadIdx.x;
    const int lane = tid & 31;
    const int warp = tid >> 5;
    const int gid  = lane >> 2;
    const int tig  = lane & 3;
    const int mrow  = (warp & 3) * 16;
    const int jbase = (warp >> 2) * 32;
    const int r0    = mrow + gid;

    const uint32_t sXa = smem_u32(sX[0]);
    const int crow0 = tid >> 3,         ccol0 = (tid & 7) * 16;
    const int crow1 = (tid + 256) >> 3;

    // ---- prologue: weights -> frags, biases ----
    uint32_t wf[2][4][4][2];
    {
        const int sr = tid >> 4;
        const int c4 = (tid & 15) << 2;
        #pragma unroll
        for (int layer = 0; layer < 2; layer++) {
            const float* W = (layer ? W1 : W0) + (size_t)g * 64 * 64;
            #pragma unroll
            for (int rr = 0; rr < 4; rr++) {
                const int row = sr + rr * 16;
                float4 w = *(const float4*)(W + (size_t)row * 64 + c4);
                *(uint2*)&sX[0][row * SW + (c4 >> 1)] =
                    make_uint2(pack2h(w.x, w.y), pack2h(w.z, w.w));
            }
            __syncthreads();
            #pragma unroll
            for (int s = 0; s < 4; s++) {
                const int jr = (jbase + s * 8 + gid) * SW;
                #pragma unroll
                for (int kc = 0; kc < 4; kc++) {
                    wf[layer][s][kc][0] = sX[0][jr + kc * 8 + tig];
                    wf[layer][s][kc][1] = sX[0][jr + kc * 8 + 4 + tig];
                }
            }
            __syncthreads();
        }
    }
    if (tid < 32)      sB0h[tid]     = pack2h(b0[(size_t)g * 64 + 2 * tid],
                                              b0[(size_t)g * 64 + 2 * tid + 1]);
    else if (tid < 96) sB1[tid - 32] = b1[(size_t)g * 64 + (tid - 32)];

    // preloop: cp.async tile 0 into sX[0]
    cpasync16(sXa + (uint32_t)(crow0 * 144 + ccol0), (const char*)xh_g + crow0 * 128 + ccol0);
    cpasync16(sXa + (uint32_t)(crow1 * 144 + ccol0), (const char*)xh_g + crow1 * 128 + ccol0);
    CP_COMMIT();

    const __half2 k02 = __half2half2(__float2half(0.2f));

    // ======== t = 0 (peeled: no L1 stream yet) ========
    {
        CP_WAIT0();
        __syncthreads();   // X(0) + biases visible
        // issue X(1) into sX[1]
        cpasync16(sXa + (uint32_t)(BUFW * 4 + crow0 * 144 + ccol0),
                  (const char*)xh_g + 8192 + crow0 * 128 + ccol0);
        cpasync16(sXa + (uint32_t)(BUFW * 4 + crow1 * 144 + ccol0),
                  (const char*)xh_g + 8192 + crow1 * 128 + ccol0);
        CP_COMMIT();

        float accA[4][4];
        #pragma unroll
        for (int s = 0; s < 4; s++)
            #pragma unroll
            for (int i = 0; i < 4; i++) accA[s][i] = 0.f;
        #pragma unroll
        for (int kc = 0; kc < 4; kc++) {
            const int kw = kc * 8 + tig;
            const uint32_t a0 = sX[0][(r0)     * SW + kw];
            const uint32_t a1 = sX[0][(r0 + 8) * SW + kw];
            const uint32_t a2 = sX[0][(r0)     * SW + kw + 4];
            const uint32_t a3 = sX[0][(r0 + 8) * SW + kw + 4];
            #pragma unroll
            for (int s = 0; s < 4; s++)
                mma_f16(accA[s][0], accA[s][1], accA[s][2], accA[s][3],
                        a0, a1, a2, a3, wf[0][s][kc][0], wf[0][s][kc][1]);
        }
        #pragma unroll
        for (int s = 0; s < 4; s++) {
            const int jw = (jbase >> 1) + s * 4 + tig;
            const __half2 hb = *(const __half2*)&sB0h[jw];
            __half2 p0 = __hadd2(__floats2half2_rn(accA[s][0], accA[s][1]), hb);
            __half2 p1 = __hadd2(__floats2half2_rn(accA[s][2], accA[s][3]), hb);
            p0 = __hmax2(p0, __hmul2(p0, k02));
            p1 = __hmax2(p1, __hmul2(p1, k02));
            sH[0][(r0)     * SW + jw] = *(uint32_t*)&p0;
            sH[0][(r0 + 8) * SW + jw] = *(uint32_t*)&p1;
        }
    }

    // ======== main pipeline: iter t runs L1(t-1) + L0(t) ========
    #pragma unroll 1
    for (int t = 1; t < NT; t++) {
        CP_WAIT0();
        __syncthreads();   // X(t) visible; h(t-1) visible; overwritten buffers quiesced

        if (t + 1 < NT) {  // issue X(t+1) into sX[(t+1)&1] (its old readers done)
            const char* src = (const char*)xh_g + (size_t)(t + 1) * 8192;
            const uint32_t dst = sXa + (uint32_t)(((t + 1) & 1) * BUFW * 4);
            cpasync16(dst + (uint32_t)(crow0 * 144 + ccol0), src + crow0 * 128 + ccol0);
            cpasync16(dst + (uint32_t)(crow1 * 144 + ccol0), src + crow1 * 128 + ccol0);
            CP_COMMIT();
        }

        const uint32_t* Hb = sH[(t - 1) & 1];
        const uint32_t* Xb = sX[t & 1];
        uint32_t*       Hn = sH[t & 1];

        // ---- L1(t-1): accB = h(t-1) * W1^T ----
        float accB[4][4];
        #pragma unroll
        for (int s = 0; s < 4; s++)
            #pragma unroll
            for (int i = 0; i < 4; i++) accB[s][i] = 0.f;
        #pragma unroll
        for (int kc = 0; kc < 4; kc++) {
            const int kw = kc * 8 + tig;
            const uint32_t a0 = Hb[(r0)     * SW + kw];
            const uint32_t a1 = Hb[(r0 + 8) * SW + kw];
            const uint32_t a2 = Hb[(r0)     * SW + kw + 4];
            const uint32_t a3 = Hb[(r0 + 8) * SW + kw + 4];
            #pragma unroll
            for (int s = 0; s < 4; s++)
                mma_f16(accB[s][0], accB[s][1], accB[s][2], accB[s][3],
                        a0, a1, a2, a3, wf[1][s][kc][0], wf[1][s][kc][1]);
        }

        // ---- L0(t): accA = X(t) * W0^T (independent stream) ----
        float accA[4][4];
        #pragma unroll
        for (int s = 0; s < 4; s++)
            #pragma unroll
            for (int i = 0; i < 4; i++) accA[s][i] = 0.f;
        #pragma unroll
        for (int kc = 0; kc < 4; kc++) {
            const int kw = kc * 8 + tig;
            const uint32_t a0 = Xb[(r0)     * SW + kw];
            const uint32_t a1 = Xb[(r0 + 8) * SW + kw];
            const uint32_t a2 = Xb[(r0)     * SW + kw + 4];
            const uint32_t a3 = Xb[(r0 + 8) * SW + kw + 4];
            #pragma unroll
            for (int s = 0; s < 4; s++)
                mma_f16(accA[s][0], accA[s][1], accA[s][2], accA[s][3],
                        a0, a1, a2, a3, wf[0][s][kc][0], wf[0][s][kc][1]);
        }

        // ---- epi1: out(t-1) ----
        {
            const int brow = (t - 1) * 64 + r0;
            #pragma unroll
            for (int s = 0; s < 4; s++) {
                const int j = jbase + s * 8 + 2 * tig;
                const float2 bb = *(const float2*)&sB1[j];
                float2 v0 = make_float2(accB[s][0] + bb.x, accB[s][1] + bb.y);
                float2 v1 = make_float2(accB[s][2] + bb.x, accB[s][3] + bb.y);
                *(float2*)(out + ((size_t)brow       * GROUPS + g) * 64 + j) = v0;
                *(float2*)(out + ((size_t)(brow + 8) * GROUPS + g) * 64 + j) = v1;
            }
        }

        // ---- epi0: h(t) -> sH[t&1] ----
        #pragma unroll
        for (int s = 0; s < 4; s++) {
            const int jw = (jbase >> 1) + s * 4 + tig;
            const __half2 hb = *(const __half2*)&sB0h[jw];
            __half2 p0 = __hadd2(__floats2half2_rn(accA[s][0], accA[s][1]), hb);
            __half2 p1 = __hadd2(__floats2half2_rn(accA[s][2], accA[s][3]), hb);
            p0 = __hmax2(p0, __hmul2(p0, k02));
            p1 = __hmax2(p1, __hmul2(p1, k02));
            Hn[(r0)     * SW + jw] = *(uint32_t*)&p0;
            Hn[(r0 + 8) * SW + jw] = *(uint32_t*)&p1;
        }
    }

    // ======== tail: L1(NT-1) ========
    __syncthreads();   // h(NT-1) visible
    {
        const uint32_t* Hb = sH[(NT - 1) & 1];
        float accB[4][4];
        #pragma unroll
        for (int s = 0; s < 4; s++)
            #pragma unroll
            for (int i = 0; i < 4; i++) accB[s][i] = 0.f;
        #pragma unroll
        for (int kc = 0; kc < 4; kc++) {
            const int kw = kc * 8 + tig;
            const uint32_t a0 = Hb[(r0)     * SW + kw];
            const uint32_t a1 = Hb[(r0 + 8) * SW + kw];
            const uint32_t a2 = Hb[(r0)     * SW + kw + 4];
            const uint32_t a3 = Hb[(r0 + 8) * SW + kw + 4];
            #pragma unroll
            for (int s = 0; s < 4; s++)
                mma_f16(accB[s][0], accB[s][1], accB[s][2], accB[s][3],
                        a0, a1, a2, a3, wf[1][s][kc][0], wf[1][s][kc][1]);
        }
        const int brow = (NT - 1) * 64 + r0;
        #pragma unroll
        for (int s = 0; s < 4; s++) {
            const int j = jbase + s * 8 + 2 * tig;
            const float2 bb = *(const float2*)&sB1[j];
            float2 v0 = make_float2(accB[s][0] + bb.x, accB[s][1] + bb.y);
            float2 v1 = make_float2(accB[s][2] + bb.x, accB[s][3] + bb.y);
            *(float2*)(out + ((size_t)brow       * GROUPS + g) * 64 + j) = v0;
            *(float2*)(out + ((size_t)(brow + 8) * GROUPS + g) * 64 + j) = v1;
        }
    }
}

extern "C" void kernel_launch(void* const* d_in, const int* in_sizes, int n_in,
                              void* d_out, int out_size) {
    const float* x  = (const float*)d_in[0];
    const float* W0 = (const float*)d_in[1];
    const float* b0 = (const float*)d_in[2];
    const float* W1 = (const float*)d_in[3];
    const float* b1 = (const float*)d_in[4];
    float* out = (float*)d_out;

    cvt_x_kernel<<<64, 256>>>(x);
    convnn_r16<<<GROUPS, 256>>>(x, W0, b0, W1, b1, out);
}

// round 17
// speedup vs baseline: 1.4616x; 1.1025x over previous
#include <cuda_runtime.h>
#include <cuda_fp16.h>
#include <cstdint>

#define GROUPS  2048
#define NT      16        // 16 iters x 64 rows
#define SW      36        // smem row stride in words (144 B)
#define BUFB    9216      // one 64-row X buffer in bytes

__device__ __align__(16) __half xh_g[1024 * 64];   // x pre-converted to fp16

__device__ __forceinline__ uint32_t pack2h(float lo, float hi) {
    __half2 h = __floats2half2_rn(lo, hi);
    return *reinterpret_cast<uint32_t*>(&h);
}
__device__ __forceinline__ uint32_t smem_u32(const void* p) {
    uint32_t a;
    asm("{ .reg .u64 t; cvta.to.shared.u64 t, %1; cvt.u32.u64 %0, t; }" : "=r"(a) : "l"(p));
    return a;
}
__device__ __forceinline__ void cpasync16(uint32_t saddr, const void* g) {
    asm volatile("cp.async.cg.shared.global [%0], [%1], 16;" :: "r"(saddr), "l"(g) : "memory");
}
#define CP_COMMIT() asm volatile("cp.async.commit_group;" ::: "memory")
#define CP_WAIT0()  asm volatile("cp.async.wait_group 0;" ::: "memory")

__device__ __forceinline__ void mma_f16(float& d0, float& d1, float& d2, float& d3,
                                        uint32_t a0, uint32_t a1, uint32_t a2, uint32_t a3,
                                        uint32_t b0, uint32_t b1) {
    asm volatile("mma.sync.aligned.m16n8k16.row.col.f32.f16.f16.f32 "
                 "{%0,%1,%2,%3}, {%4,%5,%6,%7}, {%8,%9}, {%0,%1,%2,%3};"
                 : "+f"(d0), "+f"(d1), "+f"(d2), "+f"(d3)
                 : "r"(a0), "r"(a1), "r"(a2), "r"(a3), "r"(b0), "r"(b1));
}

extern "C" __global__ void cvt_x_kernel(const float* __restrict__ x) {
    const int i = blockIdx.x * blockDim.x + threadIdx.x;   // 0..16383
    float4 v = ((const float4*)x)[i];
    ((uint2*)xh_g)[i] = make_uint2(pack2h(v.x, v.y), pack2h(v.z, v.w));
}

// 128 threads/CTA, 2 CTAs/SM, one CTA per group. 4 warps, warp tile m16 x n64:
// each warp owns ALL 64 cols of its 16 rows -> zero A-fragment duplication, and
// layer-1 A-frags are register permutations of layer-0 accumulators (C-frag
// layout == A-frag layout for m16n8k16) -> h NEVER touches shared memory.
// X staged by cp.async.cg from pre-converted fp16 x, double-buffered; exactly
// ONE __syncthreads per 64-row iteration. Both layers' weight frags in regs.
extern "C" __global__ void __launch_bounds__(128, 2) convnn_r17(
    const float* __restrict__ x,  const float* __restrict__ W0,
    const float* __restrict__ b0, const float* __restrict__ W1,
    const float* __restrict__ b1, float* __restrict__ out)
{
    __shared__ uint32_t sX[2][64 * SW];   // 2 x 9216 B
    __shared__ uint32_t sB0h[32];         // b0 as half2
    __shared__ float    sB1[64];

    const int g    = blockIdx.x;
    const int tid  = threadIdx.x;
    const int lane = tid & 31;
    const int warp = tid >> 5;     // 0..3
    const int gid  = lane >> 2;
    const int tig  = lane & 3;
    const int r0   = warp * 16 + gid;   // warp owns rows [16*warp, +16)

    const uint32_t sXa = smem_u32(sX[0]);
    // cp.async map: 512 chunks of 16B per tile, 4 per thread
    // chunk c = q*128 + tid -> row c>>3, 16B-col c&7

    // ---- prologue: stage W0/W1 (fp16) through sX[0]; warp pulls ALL 8 j-subtiles ----
    uint32_t wf[2][8][4][2];   // 128 regs
    {
        #pragma unroll
        for (int layer = 0; layer < 2; layer++) {
            const float* W = (layer ? W1 : W0) + (size_t)g * 64 * 64;
            #pragma unroll
            for (int q = 0; q < 8; q++) {
                const int f   = q * 128 + tid;   // float4 index
                const int row = f >> 4;
                const int c4  = (f & 15) << 2;
                float4 w = *(const float4*)(W + (size_t)row * 64 + c4);
                *(uint2*)&sX[0][row * SW + (c4 >> 1)] =
                    make_uint2(pack2h(w.x, w.y), pack2h(w.z, w.w));
            }
            __syncthreads();
            #pragma unroll
            for (int s = 0; s < 8; s++) {
                const int jr = (s * 8 + gid) * SW;
                #pragma unroll
                for (int kc = 0; kc < 4; kc++) {
                    wf[layer][s][kc][0] = sX[0][jr + kc * 8 + tig];
                    wf[layer][s][kc][1] = sX[0][jr + kc * 8 + 4 + tig];
                }
            }
            __syncthreads();
        }
    }
    if (tid < 32)      sB0h[tid]     = pack2h(b0[(size_t)g * 64 + 2 * tid],
                                              b0[(size_t)g * 64 + 2 * tid + 1]);
    else if (tid < 96) sB1[tid - 32] = b1[(size_t)g * 64 + (tid - 32)];

    // preloop: cp.async X(0) into sX[0]
    {
        const char* src = (const char*)xh_g;
        #pragma unroll
        for (int q = 0; q < 4; q++) {
            const int c = q * 128 + tid;
            const int row = c >> 3, col = (c & 7) * 16;
            cpasync16(sXa + (uint32_t)(row * 144 + col), src + row * 128 + col);
        }
        CP_COMMIT();
    }

    const __half2 k02 = __half2half2(__float2half(0.2f));

    #pragma unroll 1
    for (int t = 0; t < NT; t++) {
        CP_WAIT0();
        __syncthreads();   // X(t) visible; prev readers of the other buffer done

        // issue cp.async X(t+1) into the other buffer (overlaps both layers)
        if (t + 1 < NT) {
            const char* src = (const char*)xh_g + (size_t)(t + 1) * 8192;
            const uint32_t dst = sXa + (uint32_t)(((t + 1) & 1) * BUFB);
            #pragma unroll
            for (int q = 0; q < 4; q++) {
                const int c = q * 128 + tid;
                const int row = c >> 3, col = (c & 7) * 16;
                cpasync16(dst + (uint32_t)(row * 144 + col), src + row * 128 + col);
            }
            CP_COMMIT();
        }

        const uint32_t* Xb = sX[t & 1];

        // ===== layer 0: acc[s] = X * W0^T (dup-free: warp reads only its rows) =====
        float acc[8][4];
        #pragma unroll
        for (int s = 0; s < 8; s++)
            #pragma unroll
            for (int i = 0; i < 4; i++) acc[s][i] = 0.f;

        #pragma unroll
        for (int kc = 0; kc < 4; kc++) {
            const int kw = kc * 8 + tig;
            const uint32_t a0 = Xb[(r0)     * SW + kw];
            const uint32_t a1 = Xb[(r0 + 8) * SW + kw];
            const uint32_t a2 = Xb[(r0)     * SW + kw + 4];
            const uint32_t a3 = Xb[(r0 + 8) * SW + kw + 4];
            #pragma unroll
            for (int s = 0; s < 8; s++)
                mma_f16(acc[s][0], acc[s][1], acc[s][2], acc[s][3],
                        a0, a1, a2, a3, wf[0][s][kc][0], wf[0][s][kc][1]);
        }

        // ===== epilogue 0 (half2): bias + leaky; pack h into L1 A-fragments =====
        uint32_t ha[4][4];
        #pragma unroll
        for (int s = 0; s < 8; s++) {
            const __half2 hb = *(const __half2*)&sB0h[s * 4 + tig];
            __half2 p0 = __hadd2(__floats2half2_rn(acc[s][0], acc[s][1]), hb);
            __half2 p1 = __hadd2(__floats2half2_rn(acc[s][2], acc[s][3]), hb);
            p0 = __hmax2(p0, __hmul2(p0, k02));
            p1 = __hmax2(p1, __hmul2(p1, k02));
            ha[s >> 1][(s & 1) * 2 + 0] = *(uint32_t*)&p0;
            ha[s >> 1][(s & 1) * 2 + 1] = *(uint32_t*)&p1;
        }

        // ===== layer 1: acc[s] = h * W1^T (A straight from registers) =====
        #pragma unroll
        for (int s = 0; s < 8; s++)
            #pragma unroll
            for (int i = 0; i < 4; i++) acc[s][i] = 0.f;

        #pragma unroll
        for (int kc = 0; kc < 4; kc++)
            #pragma unroll
            for (int s = 0; s < 8; s++)
                mma_f16(acc[s][0], acc[s][1], acc[s][2], acc[s][3],
                        ha[kc][0], ha[kc][1], ha[kc][2], ha[kc][3],
                        wf[1][s][kc][0], wf[1][s][kc][1]);

        // ===== epilogue 1: fp32 bias, 32B-sector float2 stores =====
        const int brow = t * 64 + r0;
        #pragma unroll
        for (int s = 0; s < 8; s++) {
            const int j = s * 8 + 2 * tig;
            const float2 bb = *(const float2*)&sB1[j];
            float2 v0 = make_float2(acc[s][0] + bb.x, acc[s][1] + bb.y);
            float2 v1 = make_float2(acc[s][2] + bb.x, acc[s][3] + bb.y);
            *(float2*)(out + ((size_t)brow       * GROUPS + g) * 64 + j) = v0;
            *(float2*)(out + ((size_t)(brow + 8) * GROUPS + g) * 64 + j) = v1;
        }
    }
}

extern "C" void kernel_launch(void* const* d_in, const int* in_sizes, int n_in,
                              void* d_out, int out_size) {
    const float* x  = (const float*)d_in[0];
    const float* W0 = (const float*)d_in[1];
    const float* b0 = (const float*)d_in[2];
    const float* W1 = (const float*)d_in[3];
    const float* b1 = (const float*)d_in[4];
    float* out = (float*)d_out;

    cvt_x_kernel<<<64, 256>>>(x);
    convnn_r17<<<GROUPS, 128>>>(x, W0, b0, W1, b1, out);
}